// round 3
// baseline (speedup 1.0000x reference)
#include <cuda_runtime.h>

// Output layout (floats), tuple order (c_all, y_all, GBT_A, GBT_B):
//   c_all : [1024,256]      offset 0        size 262144
//   y_all : [1024]          offset 262144   size 1024
//   GBT_A : [1024,256,256]  offset 263168   size 67108864
//   GBT_B : [1024,256]      offset 67372032 size 262144
#define OC 0
#define OY 262144
#define OA 263168
#define OB 67372032

static __device__ __forceinline__ float frcp(float x) {
    float y; asm("rcp.approx.ftz.f32 %0,%1;" : "=f"(y) : "f"(x)); return y;
}

__global__ __launch_bounds__(256) void hippo_fused(
    const float* __restrict__ f,
    const float* __restrict__ init_state,
    const float* __restrict__ Bv,
    float* __restrict__ out)
{
    const int bid = blockIdx.x;
    const int tid = threadIdx.x;

    if (bid < 1024) {
        // ============ GBT_A: ONE timestep per block, one column per thread ====
        // Ad_k lower triangular. Column j:
        //   diag    = (1 - h(j+1)) / d_j
        //   start   = Ad_{j+1,j} = -2h r_{j+1} r_j / (d_j d_{j+1})
        //   ratio   t_i = r_i (1 - h(i-1)) / (r_{i-1} d_i)  (column-independent)
        __shared__ float t_sh[256];
        const int k = bid;
        const int j = tid;
        const float s = frcp((float)(k + 1));
        const float h = 0.5f * s;

        {
            float tv = 0.0f;
            if (j >= 1) {
                float ri  = __ldg(Bv + j);
                float rim = __ldg(Bv + j - 1);
                float di  = fmaf(h, (float)(j + 1), 1.0f);
                tv = ri * (1.0f - h * (float)(j - 1)) * frcp(rim * di);
            }
            t_sh[j] = tv;
        }

        const float invdj  = frcp(fmaf(h, (float)(j + 1), 1.0f));
        const float invdj1 = frcp(fmaf(h, (float)(j + 2), 1.0f));
        const float diag   = (1.0f - h * (float)(j + 1)) * invdj;
        const float rj     = __ldg(Bv + j);
        const float rj1    = (j + 1 < 256) ? __ldg(Bv + j + 1) : 0.0f;
        const float start  = -2.0f * h * rj1 * rj * invdj * invdj1;
        __syncthreads();

        float* outp = out + OA + ((size_t)k << 16) + j;
        const float4* t4 = (const float4*)t_sh;
        float val = 0.0f;
        #pragma unroll 4
        for (int i4 = 0; i4 < 64; i4++) {
            float4 tv = t4[i4];
            int i = i4 << 2;
            #pragma unroll
            for (int m = 0; m < 4; m++) {
                float t  = (&tv.x)[m];
                int   ii = i + m;
                val = (ii == j + 1) ? start : val * t;   // stays 0 until ii==j+1
                float o = (ii < j) ? 0.0f : ((ii == j) ? diag : val);
                outp[(size_t)ii << 8] = o;               // coalesced: warp = 128B line
            }
        }
    } else if (bid == 1024) {
        // ================= systolic scan: c_all + y_all =================
        // c_k = P1_k^{-1}(2 c_{k-1} + s_k f_k B) - c_{k-1}; O(N) solve via
        //   x_i = (u_i - h r_i S_i)/d_i ;  S_{i+1} = S_i + r_i x_i
        // lane l owns element i=l; iteration t handles timestep k = t - l.
        __shared__ float2 tab[1024];   // (s_k, s_k*f_k)
        __shared__ float2 bnd[2][8];   // warp-boundary (S, ypartial), double buffered
        const int w = tid >> 5, lane = tid & 31;

        for (int kk = tid; kk < 1024; kk += 256) {
            float sk = frcp((float)(kk + 1));
            tab[kk] = make_float2(sk, sk * f[kk]);
        }
        if (tid < 16) ((float2*)bnd)[tid] = make_float2(0.0f, 0.0f);

        const float r    = __ldg(Bv + tid);       // r_i = B_i
        const float fip1 = (float)(tid + 1);
        float c = init_state[tid];
        float Scur = 0.0f, ycur = 0.0f;
        __syncthreads();

        int k = -tid;
        for (int t = 0; t < 1279; t++, k++) {
            bool valid = ((unsigned)k < 1024u);
            float2 ssf = tab[valid ? k : 0];
            float h    = 0.5f * ssf.x;
            float invd = frcp(fmaf(h, fip1, 1.0f));
            float u    = fmaf(ssf.y, r, c + c);          // 2c + s f B_i
            float hr   = h * r;
            float x    = fmaf(-hr, Scur, u) * invd;
            float So   = fmaf(r, x, Scur);
            float cn   = x - c;
            float yo   = ycur + cn;
            if (valid) {
                c = cn;
                out[OC + ((size_t)k << 8) + tid] = cn;
                if (tid == 255) out[OY + k] = yo;        // y_k completes at element 255
            }
            float Ssh = __shfl_up_sync(0xffffffffu, So, 1);
            float ysh = __shfl_up_sync(0xffffffffu, yo, 1);
            if (lane == 31) bnd[t & 1][w] = make_float2(So, yo);
            __syncthreads();
            if (lane == 0) {
                if (w == 0) { Ssh = 0.0f; ysh = 0.0f; }
                else { float2 b = bnd[t & 1][w - 1]; Ssh = b.x; ysh = b.y; }
            }
            Scur = Ssh; ycur = ysh;
        }
    } else {
        // ================= GBT_B: thread per timestep =================
        __shared__ float rsh[256];
        rsh[tid] = __ldg(Bv + tid);
        __syncthreads();
        const int k = ((bid - 1025) << 8) + tid;
        const float s = frcp((float)(k + 1));
        const float h = 0.5f * s;
        float S = 0.0f;
        float* outB = out + OB + ((size_t)k << 8);
        for (int i = 0; i < 256; i++) {
            float r    = rsh[i];
            float invd = frcp(fmaf(h, (float)(i + 1), 1.0f));
            float x    = r * fmaf(-h, S, 1.0f) * invd;   // (r_i - h r_i S)/d_i
            outB[i] = s * x;
            S = fmaf(r, x, S);
        }
    }
}

extern "C" void kernel_launch(void* const* d_in, const int* in_sizes, int n_in,
                              void* d_out, int out_size) {
    const float* f          = (const float*)d_in[0];
    const float* init_state = (const float*)d_in[1];
    const float* Bv         = (const float*)d_in[3];
    hippo_fused<<<1029, 256>>>(f, init_state, Bv, (float*)d_out);
}

// round 5
// speedup vs baseline: 1.3329x; 1.3329x over previous
#include <cuda_runtime.h>

// Output layout (floats), tuple order (c_all, y_all, GBT_A, GBT_B):
//   c_all : [1024,256]      offset 0        size 262144
//   y_all : [1024]          offset 262144   size 1024
//   GBT_A : [1024,256,256]  offset 263168   size 67108864
//   GBT_B : [1024,256]      offset 67372032 size 262144
#define OC 0
#define OY 262144
#define OA 263168
#define OB 67372032

#define RING 192
#define SMEM_BYTES (8192 + 196608 + 32)   // tab | ring | bnd

static __device__ __forceinline__ float frcp(float x) {
    float y; asm("rcp.approx.ftz.f32 %0,%1;" : "=f"(y) : "f"(x)); return y;
}

__global__ __launch_bounds__(256) void hippo_fused(
    const float* __restrict__ f,
    const float* __restrict__ init_state,
    const float* __restrict__ Bv,
    float* __restrict__ out)
{
    extern __shared__ char dsm[];
    const int bid = blockIdx.x;
    const int tid = threadIdx.x;

    if (bid == 0) {
        // ========== scan block: c_all + y_all (dedicated SM) ==========
        // c_k = P1_k^{-1}(2 c_{k-1} + s_k f_k B) - c_{k-1}; O(N) solve:
        //   x_i = (u_i - h r_i S_i)/d_i ;  S_{i+1} = S_i + r_i x_i
        // 64 wavefront lanes (2 warps), lane gl owns i in [4gl,4gl+4),
        // B=2 timesteps per super-iteration; 575 super-iterations.
        float2* tab = (float2*)dsm;                      // (s*f, h) per k
        float*  ring = (float*)(dsm + 8192);             // [RING][256]
        float4* bnd  = (float4*)(dsm + 8192 + 196608);   // [2] parity

        for (int kq = tid; kq < 1024; kq += 256) {
            float s = frcp((float)(kq + 1));
            tab[kq] = make_float2(s * f[kq], 0.5f * s);
        }
        __syncthreads();

        const int w = tid >> 5, lane = tid & 31;
        if (w < 2) {
            const int gl = (w << 5) + lane;              // 0..63
            float rr[4], cc[4];
            {
                float4 r4 = *(const float4*)(Bv + 4 * gl);
                float4 c4 = *(const float4*)(init_state + 4 * gl);
                rr[0]=r4.x; rr[1]=r4.y; rr[2]=r4.z; rr[3]=r4.w;
                cc[0]=c4.x; cc[1]=c4.y; cc[2]=c4.z; cc[3]=c4.w;
            }
            float ip1[4];
            #pragma unroll
            for (int m = 0; m < 4; m++) ip1[m] = (float)(4 * gl + m + 1);

            float Sin0 = 0.f, Yin0 = 0.f, Sin1 = 0.f, Yin1 = 0.f;

            for (int T = 0; T < 575; T++) {
                const int kk = 2 * (T - gl);
                const bool valid = ((unsigned)(T - gl) < 512u);
                const int ki = valid ? kk : 0;
                float So0, Yo0, So1, Yo1;
                float4 st0, st1;
                {   // k = kk
                    float2 th = tab[ki];
                    float sf = th.x, h = th.y;
                    float S = Sin0, y = Yin0;
                    #pragma unroll
                    for (int m = 0; m < 4; m++) {
                        float invd = frcp(fmaf(h, ip1[m], 1.0f));
                        float u  = fmaf(sf, rr[m], cc[m] + cc[m]);
                        float hr = h * rr[m];
                        float x  = fmaf(-hr, S, u) * invd;
                        S = fmaf(rr[m], x, S);
                        float cn = x - cc[m];
                        if (valid) cc[m] = cn;
                        y += cn;
                        (&st0.x)[m] = cn;
                    }
                    So0 = S; Yo0 = y;
                }
                {   // k = kk+1
                    float2 th = tab[valid ? (kk + 1) : 0];
                    float sf = th.x, h = th.y;
                    float S = Sin1, y = Yin1;
                    #pragma unroll
                    for (int m = 0; m < 4; m++) {
                        float invd = frcp(fmaf(h, ip1[m], 1.0f));
                        float u  = fmaf(sf, rr[m], cc[m] + cc[m]);
                        float hr = h * rr[m];
                        float x  = fmaf(-hr, S, u) * invd;
                        S = fmaf(rr[m], x, S);
                        float cn = x - cc[m];
                        if (valid) cc[m] = cn;
                        y += cn;
                        (&st1.x)[m] = cn;
                    }
                    So1 = S; Yo1 = y;
                }
                if (valid) {
                    unsigned r0 = (unsigned)kk % RING;
                    unsigned r1 = (unsigned)(kk + 1) % RING;
                    *(float4*)(ring + r0 * 256 + 4 * gl) = st0;
                    *(float4*)(ring + r1 * 256 + 4 * gl) = st1;
                    if (gl == 63) { out[OY + kk] = Yo0; out[OY + kk + 1] = Yo1; }
                }
                float ns0 = __shfl_up_sync(0xffffffffu, So0, 1);
                float ny0 = __shfl_up_sync(0xffffffffu, Yo0, 1);
                float ns1 = __shfl_up_sync(0xffffffffu, So1, 1);
                float ny1 = __shfl_up_sync(0xffffffffu, Yo1, 1);
                if (w == 0 && lane == 31)
                    bnd[T & 1] = make_float4(So0, Yo0, So1, Yo1);
                __syncthreads();
                if (lane == 0) {
                    if (w == 0) { ns0 = 0.f; ny0 = 0.f; ns1 = 0.f; ny1 = 0.f; }
                    else { float4 b = bnd[T & 1]; ns0 = b.x; ny0 = b.y; ns1 = b.z; ny1 = b.w; }
                }
                Sin0 = ns0; Yin0 = ny0; Sin1 = ns1; Yin1 = ny1;
            }
        } else {
            // flush warps: after bar T, rows 2(T-63), 2(T-63)+1 are complete.
            for (int T = 0; T < 575; T++) {
                __syncthreads();
                if (w == 2 || w == 3) {
                    int row = 2 * (T - 63) + (w - 2);
                    if (row >= 0 && row < 1024) {
                        const float* src = ring + ((unsigned)row % RING) * 256;
                        float* dst = out + OC + ((size_t)row << 8);
                        float4 a = *(const float4*)(src + 4 * lane);
                        float4 b = *(const float4*)(src + 128 + 4 * lane);
                        *(float4*)(dst + 4 * lane) = a;
                        *(float4*)(dst + 128 + 4 * lane) = b;
                    }
                }
            }
        }
    } else if (bid <= 128) {
        // ========== GBT_A sweep: 8 timesteps per block (two passes) ======
        __shared__ float t_sh[4][256];
        const int grp = tid >> 6;       // timestep within pass
        const int g   = tid & 63;       // owns 4 columns
        for (int pass = 0; pass < 2; pass++) {
            const int k = ((bid - 1) << 3) + (pass << 2) + grp;
            const float s = frcp((float)(k + 1));
            const float h = 0.5f * s;

            #pragma unroll
            for (int m = 0; m < 4; m++) {
                int i = g + (m << 6);
                float tv = 0.0f;
                if (i >= 1) {
                    float ri  = __ldg(Bv + i);
                    float rim = __ldg(Bv + i - 1);
                    float di  = fmaf(h, (float)(i + 1), 1.0f);
                    tv = ri * (1.0f - h * (float)(i - 1)) * frcp(rim * di);
                }
                t_sh[grp][i] = tv;
            }
            __syncthreads();

            const int j0 = g << 2;
            float invd[5];
            #pragma unroll
            for (int m = 0; m < 5; m++)
                invd[m] = frcp(fmaf(h, (float)(j0 + m + 1), 1.0f));

            float diag[4], start[4], val[4];
            #pragma unroll
            for (int m = 0; m < 4; m++) {
                int j = j0 + m;
                diag[m] = (1.0f - h * (float)(j + 1)) * invd[m];
                float rj  = __ldg(Bv + j);
                float rj1 = (j + 1 < 256) ? __ldg(Bv + j + 1) : 0.0f;
                start[m] = -2.0f * h * rj1 * rj * invd[m] * invd[m + 1];
                val[m] = 0.0f;
            }

            float4* outp = (float4*)(out + OA + ((size_t)k << 16) + j0);
            for (int i = 0; i < 256; i++) {
                float tv = t_sh[grp][i];
                float4 v;
                #pragma unroll
                for (int m = 0; m < 4; m++) {
                    int j = j0 + m;
                    val[m] = (i == j + 1) ? start[m] : val[m] * tv;
                    float vv = (i < j) ? 0.0f : ((i == j) ? diag[m] : val[m]);
                    ((float*)&v)[m] = vv;
                }
                outp[(size_t)i << 6] = v;
            }
            __syncthreads();
        }
    } else {
        // ========== GBT_B: thread per timestep ==========
        __shared__ float rsh[256];
        rsh[tid] = __ldg(Bv + tid);
        __syncthreads();
        const int k = ((bid - 129) << 8) + tid;
        const float s = frcp((float)(k + 1));
        const float h = 0.5f * s;
        float S = 0.0f;
        float* outB = out + OB + ((size_t)k << 8);
        for (int i = 0; i < 256; i++) {
            float r    = rsh[i];
            float invd = frcp(fmaf(h, (float)(i + 1), 1.0f));
            float x    = r * fmaf(-h, S, 1.0f) * invd;
            outB[i] = s * x;
            S = fmaf(r, x, S);
        }
    }
}

extern "C" void kernel_launch(void* const* d_in, const int* in_sizes, int n_in,
                              void* d_out, int out_size) {
    const float* f          = (const float*)d_in[0];
    const float* init_state = (const float*)d_in[1];
    const float* Bv         = (const float*)d_in[3];
    cudaFuncSetAttribute(hippo_fused, cudaFuncAttributeMaxDynamicSharedMemorySize,
                         SMEM_BYTES);
    hippo_fused<<<133, 256, SMEM_BYTES>>>(f, init_state, Bv, (float*)d_out);
}